// round 6
// baseline (speedup 1.0000x reference)
#include <cuda_runtime.h>
#include <cuda_bf16.h>
#include <cstdint>

#define N_NODES 50000
#define N_EDGES 800000
#define D_IN    256
#define D_HID   256
#define D_OUT   128
#define GRID_M  391            // ceil(50000/128)
#define HISTB   3125           // ceil(800000/256)

// ---------------- scratch (static device globals; no allocation) -------------
__device__ float g_H1[(size_t)N_NODES * D_HID];
__device__ float g_H2[(size_t)N_NODES * D_HID];
__device__ float g_H3[(size_t)N_NODES * D_OUT];
__device__ __nv_bfloat16 g_W1Th[D_HID * D_IN];
__device__ __nv_bfloat16 g_W1Tl[D_HID * D_IN];
__device__ __nv_bfloat16 g_W2Th[D_OUT * D_HID];
__device__ __nv_bfloat16 g_W2Tl[D_OUT * D_HID];
__device__ int   g_rowptr[N_NODES + 1];
__device__ int   g_cursor[N_NODES];
__device__ int   g_bsum[256];
__device__ int2  g_ecv[N_EDGES];   // packed {col, val_bits}

// ---------------- K1: histogram + transpose/split W1, W2 ---------------------
__global__ void k_hist_init(const int* __restrict__ erow,
                            const float* __restrict__ W1,
                            const float* __restrict__ W2) {
    int b = blockIdx.x;
    if (b < HISTB) {
        int i = b * 256 + threadIdx.x;
        if (i < N_EDGES) atomicAdd(&g_rowptr[erow[i] + 1], 1);
        return;
    }
    b -= HISTB;
    if (b < 256) {               // W1: 65536 elems
        int i = b * 256 + threadIdx.x;
        int r = i >> 8, c = i & 255;      // D_HID = 256
        float v = W1[i];
        __nv_bfloat16 h = __float2bfloat16(v);
        g_W1Th[(size_t)c * D_IN + r] = h;
        g_W1Tl[(size_t)c * D_IN + r] = __float2bfloat16(v - __bfloat162float(h));
        return;
    }
    b -= 256;
    {                            // W2: 32768 elems
        int i = b * 256 + threadIdx.x;
        int r = i >> 7, c = i & 127;      // D_OUT = 128
        float v = W2[i];
        __nv_bfloat16 h = __float2bfloat16(v);
        g_W2Th[(size_t)c * D_HID + r] = h;
        g_W2Tl[(size_t)c * D_HID + r] = __float2bfloat16(v - __bfloat162float(h));
    }
}

// ---------------- parallel scan: 2 phases ------------------------------------
__global__ void k_scan1() {   // 196 blocks x 256: block-local inclusive scan
    __shared__ int sh[256];
    int t = threadIdx.x;
    int idx = blockIdx.x * 256 + t;
    int v = (idx < N_NODES + 1) ? g_rowptr[idx] : 0;
    sh[t] = v;
    __syncthreads();
#pragma unroll
    for (int off = 1; off < 256; off <<= 1) {
        int u = (t >= off) ? sh[t - off] : 0;
        __syncthreads();
        sh[t] += u;
        __syncthreads();
    }
    if (idx < N_NODES + 1) g_rowptr[idx] = sh[t];
    if (t == 255) g_bsum[blockIdx.x] = sh[255];
}

__global__ void k_scan3() {   // 196 blocks: each computes its own offset, applies
    __shared__ int sh[256];
    int t = threadIdx.x;
    sh[t] = (t < (int)blockIdx.x) ? g_bsum[t] : 0;
    __syncthreads();
#pragma unroll
    for (int off = 128; off > 0; off >>= 1) {
        if (t < off) sh[t] += sh[t + off];
        __syncthreads();
    }
    int offset = sh[0];
    int idx = blockIdx.x * 256 + t;
    if (idx < N_NODES + 1) {
        int v = g_rowptr[idx] + offset;
        g_rowptr[idx] = v;
        if (idx < N_NODES) g_cursor[idx] = v;
    }
}

// ---------------- HMMA GEMM body (ldmatrix fragments) ------------------------
__device__ __forceinline__ void mma_bf16(float* c, const uint32_t* a, const uint32_t* b) {
    asm("mma.sync.aligned.m16n8k16.row.col.f32.bf16.bf16.f32 "
        "{%0,%1,%2,%3}, {%4,%5,%6,%7}, {%8,%9}, {%0,%1,%2,%3};"
        : "+f"(c[0]), "+f"(c[1]), "+f"(c[2]), "+f"(c[3])
        : "r"(a[0]), "r"(a[1]), "r"(a[2]), "r"(a[3]), "r"(b[0]), "r"(b[1]));
}

#define LDSM4(r0, r1, r2, r3, addr)                                            \
    asm volatile("ldmatrix.sync.aligned.m8n8.x4.shared.b16 {%0,%1,%2,%3}, [%4];" \
                 : "=r"(r0), "=r"(r1), "=r"(r2), "=r"(r3) : "r"(addr))

// A: f32 [M][ldab] (split on the fly). B: pre-split bf16 [*][ldab].
// CTA 128x128, BK=32, 8 warps (64x32 warp tiles), mma.sync.m16n8k16.
template <bool ACC>
__device__ __forceinline__ void gemm_body(
    const float* __restrict__ A, const __nv_bfloat16* __restrict__ Bh,
    const __nv_bfloat16* __restrict__ Bl, float* __restrict__ C,
    int M, int N, int ldab, int kLen, int bx, int by)
{
    const int SP = 40;   // smem row stride (80 B): conflict-free for ldmatrix
    __shared__ __nv_bfloat16 sAh[128][SP];
    __shared__ __nv_bfloat16 sAl[128][SP];
    __shared__ __nv_bfloat16 sBh[128][SP];
    __shared__ __nv_bfloat16 sBl[128][SP];

    int tid = threadIdx.x;
    int lane = tid & 31, wid = tid >> 5;
    int rowBase = by * 128, colBase = bx * 128;
    int wm = (wid >> 2) * 64;
    int wn = (wid & 3) * 32;

    float acc[4][4][4];
#pragma unroll
    for (int mi = 0; mi < 4; mi++)
#pragma unroll
        for (int ni = 0; ni < 4; ni++)
#pragma unroll
            for (int q = 0; q < 4; q++) acc[mi][ni][q] = 0.f;

    uint32_t aHiB = (uint32_t)__cvta_generic_to_shared(&sAh[0][0]);
    uint32_t aLoB = (uint32_t)__cvta_generic_to_shared(&sAl[0][0]);
    uint32_t bHiB = (uint32_t)__cvta_generic_to_shared(&sBh[0][0]);
    uint32_t bLoB = (uint32_t)__cvta_generic_to_shared(&sBl[0][0]);

    uint32_t aOff[4], bOff[2];
    {
        int ra = ((lane & 8) ? 8 : 0) + (lane & 7);
        int ca = (lane & 16) ? 8 : 0;
#pragma unroll
        for (int mi = 0; mi < 4; mi++)
            aOff[mi] = (uint32_t)(((wm + mi * 16 + ra) * SP + ca) * 2);
        int rb = (lane & 7) + ((lane & 16) ? 8 : 0);
        int cb = (lane & 8) ? 8 : 0;
#pragma unroll
        for (int p = 0; p < 2; p++)
            bOff[p] = (uint32_t)(((wn + p * 16 + rb) * SP + cb) * 2);
    }

    for (int k0 = 0; k0 < kLen; k0 += 32) {
        // ---- A tile: load f32, split to bf16 hi/lo (128 rows x 32 k)
#pragma unroll
        for (int it = 0; it < 4; it++) {
            int ch = tid + it * 256;
            int r = ch >> 3, c = ch & 7;
            int gr = rowBase + r;
            float4 f = make_float4(0.f, 0.f, 0.f, 0.f);
            if (gr < M) f = *(const float4*)(A + (size_t)gr * ldab + k0 + c * 4);
            __nv_bfloat162 h01 = __floats2bfloat162_rn(f.x, f.y);
            __nv_bfloat162 h23 = __floats2bfloat162_rn(f.z, f.w);
            float2 g01 = __bfloat1622float2(h01);
            float2 g23 = __bfloat1622float2(h23);
            __nv_bfloat162 l01 = __floats2bfloat162_rn(f.x - g01.x, f.y - g01.y);
            __nv_bfloat162 l23 = __floats2bfloat162_rn(f.z - g23.x, f.w - g23.y);
            uint2 uh, ul;
            uh.x = *(uint32_t*)&h01; uh.y = *(uint32_t*)&h23;
            ul.x = *(uint32_t*)&l01; ul.y = *(uint32_t*)&l23;
            *(uint2*)&sAh[r][c * 4] = uh;
            *(uint2*)&sAl[r][c * 4] = ul;
        }
        // ---- B tile: copy pre-split bf16 (128 n x 32 k)
#pragma unroll
        for (int it = 0; it < 2; it++) {
            int ch = tid + it * 256;
            int r = ch >> 2, c = ch & 3;
            int gc = colBase + r;
            uint4 vh = *(const uint4*)(Bh + (size_t)gc * ldab + k0 + c * 8);
            uint4 vl = *(const uint4*)(Bl + (size_t)gc * ldab + k0 + c * 8);
            *(uint4*)&sBh[r][c * 8] = vh;
            *(uint4*)&sBl[r][c * 8] = vl;
        }
        __syncthreads();

#pragma unroll
        for (int ks = 0; ks < 2; ks++) {
            uint32_t kb = (uint32_t)(ks * 32);
            uint32_t bhr[8], blr[8];
            LDSM4(bhr[0], bhr[1], bhr[2], bhr[3], bHiB + bOff[0] + kb);
            LDSM4(bhr[4], bhr[5], bhr[6], bhr[7], bHiB + bOff[1] + kb);
            LDSM4(blr[0], blr[1], blr[2], blr[3], bLoB + bOff[0] + kb);
            LDSM4(blr[4], blr[5], blr[6], blr[7], bLoB + bOff[1] + kb);
#pragma unroll
            for (int mi = 0; mi < 4; mi++) {
                uint32_t ah[4], al[4];
                LDSM4(ah[0], ah[1], ah[2], ah[3], aHiB + aOff[mi] + kb);
                LDSM4(al[0], al[1], al[2], al[3], aLoB + aOff[mi] + kb);
#pragma unroll
                for (int ni = 0; ni < 4; ni++) {
                    mma_bf16(acc[mi][ni], ah, &bhr[ni * 2]);
                    mma_bf16(acc[mi][ni], ah, &blr[ni * 2]);
                    mma_bf16(acc[mi][ni], al, &bhr[ni * 2]);
                }
            }
        }
        __syncthreads();
    }

#pragma unroll
    for (int mi = 0; mi < 4; mi++) {
        int rr = rowBase + wm + mi * 16 + (lane >> 2);
#pragma unroll
        for (int ni = 0; ni < 4; ni++) {
            int cc = colBase + wn + ni * 8 + (lane & 3) * 2;
            if (rr < M) {
                float2 v = make_float2(acc[mi][ni][0], acc[mi][ni][1]);
                float2* p = (float2*)&C[(size_t)rr * N + cc];
                if (ACC) { float2 o = *p; v.x += o.x; v.y += o.y; }
                *p = v;
            }
            if (rr + 8 < M) {
                float2 v = make_float2(acc[mi][ni][2], acc[mi][ni][3]);
                float2* p = (float2*)&C[(size_t)(rr + 8) * N + cc];
                if (ACC) { float2 o = *p; v.x += o.x; v.y += o.y; }
                *p = v;
            }
        }
    }
}

// ---------------- SpMM body: 1 warp per row, 32 feature-lanes of float4 ------
template <bool RELU>
__device__ __forceinline__ void spmm_body(const float* __restrict__ X,
                                          float* __restrict__ Yout,
                                          int stride, int blk) {
    int tid = threadIdx.x;
    int f4 = (tid & 31) * 4;
    int r = blk * 8 + (tid >> 5);
    if (r >= N_NODES) return;
    int e   = g_rowptr[r];
    int end = g_rowptr[r + 1];
    float4 acc = make_float4(0.f, 0.f, 0.f, 0.f);
    // 4-wide software pipeline: 4 gathers in flight per thread
    for (; e + 4 <= end; e += 4) {
        int2 cv0 = __ldg(&g_ecv[e]);
        int2 cv1 = __ldg(&g_ecv[e + 1]);
        int2 cv2 = __ldg(&g_ecv[e + 2]);
        int2 cv3 = __ldg(&g_ecv[e + 3]);
        float4 x0 = __ldg((const float4*)&X[(size_t)cv0.x * stride + f4]);
        float4 x1 = __ldg((const float4*)&X[(size_t)cv1.x * stride + f4]);
        float4 x2 = __ldg((const float4*)&X[(size_t)cv2.x * stride + f4]);
        float4 x3 = __ldg((const float4*)&X[(size_t)cv3.x * stride + f4]);
        float v0 = __int_as_float(cv0.y), v1 = __int_as_float(cv1.y);
        float v2 = __int_as_float(cv2.y), v3 = __int_as_float(cv3.y);
        acc.x += v0 * x0.x; acc.y += v0 * x0.y; acc.z += v0 * x0.z; acc.w += v0 * x0.w;
        acc.x += v1 * x1.x; acc.y += v1 * x1.y; acc.z += v1 * x1.z; acc.w += v1 * x1.w;
        acc.x += v2 * x2.x; acc.y += v2 * x2.y; acc.z += v2 * x2.z; acc.w += v2 * x2.w;
        acc.x += v3 * x3.x; acc.y += v3 * x3.y; acc.z += v3 * x3.z; acc.w += v3 * x3.w;
    }
    for (; e < end; e++) {
        int2 cv = __ldg(&g_ecv[e]);
        float v = __int_as_float(cv.y);
        float4 x = __ldg((const float4*)&X[(size_t)cv.x * stride + f4]);
        acc.x += v * x.x; acc.y += v * x.y; acc.z += v * x.z; acc.w += v * x.w;
    }
    if (RELU) {
        acc.x = fmaxf(acc.x, 0.f); acc.y = fmaxf(acc.y, 0.f);
        acc.z = fmaxf(acc.z, 0.f); acc.w = fmaxf(acc.w, 0.f);
    }
    *(float4*)&Yout[(size_t)r * stride + f4] = acc;
}

// ---------------- fused pipeline kernels --------------------------------------
__global__ __launch_bounds__(256, 2)
void k_g1a_scatter(const float* __restrict__ Y, float* __restrict__ H1,
                   const int* __restrict__ erow, const int* __restrict__ ecol,
                   const float* __restrict__ eval)
{
    if (blockIdx.x < GRID_M) {
        gemm_body<false>(Y, g_W1Th, g_W1Tl, H1, N_NODES, D_HID, 256, 256,
                         0, blockIdx.x);
    } else {
        int i = (blockIdx.x - GRID_M) * 256 + threadIdx.x;
        if (i < N_EDGES) {
            int r = erow[i];
            int p = atomicAdd(&g_cursor[r], 1);
            g_ecv[p] = make_int2(ecol[i], __float_as_int(eval[i]));
        }
    }
}

__global__ __launch_bounds__(256, 2)
void k_g1b_spmm1a(const float* __restrict__ Y, float* __restrict__ H1,
                  float* __restrict__ H2)
{
    if (blockIdx.x < GRID_M) {
        gemm_body<false>(Y, g_W1Th, g_W1Tl, H1, N_NODES, D_HID, 256, 256,
                         1, blockIdx.x);
    } else {
        spmm_body<true>(H1, H2, 256, blockIdx.x - GRID_M);
    }
}

__global__ __launch_bounds__(256, 2)
void k_spmm1b_g2a(const float* __restrict__ H1, float* __restrict__ H2,
                  float* __restrict__ H3)
{
    if (blockIdx.x < GRID_M) {
        gemm_body<false>(H2, g_W2Th, g_W2Tl, H3, N_NODES, D_OUT, 256, 128,
                         0, blockIdx.x);
    } else {
        spmm_body<true>(H1 + 128, H2 + 128, 256, blockIdx.x - GRID_M);
    }
}

__global__ __launch_bounds__(256, 2)
void k_g2b(const float* __restrict__ H2, float* __restrict__ H3)
{
    gemm_body<true>(H2 + 128, g_W2Th + 128, g_W2Tl + 128, H3, N_NODES, D_OUT,
                    256, 128, 0, blockIdx.x);
}

__global__ __launch_bounds__(256)
void k_spmm2(const float* __restrict__ H3, float* __restrict__ out)
{
    spmm_body<false>(H3, out, 128, blockIdx.x);
}

// ---------------- launch ------------------------------------------------------
extern "C" void kernel_launch(void* const* d_in, const int* in_sizes, int n_in,
                              void* d_out, int out_size) {
    const float* Y        = (const float*)d_in[0];
    const int*   edge_row = (const int*)d_in[1];
    const int*   edge_col = (const int*)d_in[2];
    const float* edge_val = (const float*)d_in[3];
    const float* W1       = (const float*)d_in[4];
    const float* W2       = (const float*)d_in[5];
    float*       out      = (float*)d_out;

    float *pH1, *pH2, *pH3;
    int *pRowptr;
    cudaGetSymbolAddress((void**)&pH1, g_H1);
    cudaGetSymbolAddress((void**)&pH2, g_H2);
    cudaGetSymbolAddress((void**)&pH3, g_H3);
    cudaGetSymbolAddress((void**)&pRowptr, g_rowptr);

    const int SPMM_G = (N_NODES + 7) / 8;   // 6250

    cudaMemsetAsync(pRowptr, 0, (N_NODES + 1) * sizeof(int));
    k_hist_init<<<HISTB + 256 + 128, 256>>>(edge_row, W1, W2);
    k_scan1<<<196, 256>>>();
    k_scan3<<<196, 256>>>();
    k_g1a_scatter<<<GRID_M + HISTB, 256>>>(Y, pH1, edge_row, edge_col, edge_val);
    k_g1b_spmm1a<<<GRID_M + SPMM_G, 256>>>(Y, pH1, pH2);
    k_spmm1b_g2a<<<GRID_M + SPMM_G, 256>>>(pH1, pH2, pH3);
    k_g2b<<<GRID_M, 256>>>(pH2, pH3);
    k_spmm2<<<SPMM_G, 256>>>(pH3, out);
}

// round 7
// speedup vs baseline: 1.4795x; 1.4795x over previous
#include <cuda_runtime.h>
#include <cuda_bf16.h>
#include <cstdint>

#define N_NODES 50000
#define N_EDGES 800000
#define D_IN    256
#define D_HID   256
#define D_OUT   128
#define GRID_M  391            // ceil(50000/128)
#define HISTB   3125           // ceil(800000/256)
#define YSPB    12500          // 50000*256/4 float4 / 256 threads

// ---------------- scratch ------------------------------------------------------
__device__ float g_H1[(size_t)N_NODES * D_HID];
__device__ __nv_bfloat16 g_H2h[(size_t)N_NODES * D_HID];
__device__ __nv_bfloat16 g_H2l[(size_t)N_NODES * D_HID];
__device__ float g_H3[(size_t)N_NODES * D_OUT];
__device__ __nv_bfloat16 g_Yh[(size_t)N_NODES * D_IN];
__device__ __nv_bfloat16 g_Yl[(size_t)N_NODES * D_IN];
__device__ __nv_bfloat16 g_W1Th[D_HID * D_IN];
__device__ __nv_bfloat16 g_W1Tl[D_HID * D_IN];
__device__ __nv_bfloat16 g_W2Th[D_OUT * D_HID];
__device__ __nv_bfloat16 g_W2Tl[D_OUT * D_HID];
__device__ int   g_rowptr[N_NODES + 1];
__device__ int   g_cursor[N_NODES];
__device__ int   g_bsum[256];
__device__ int2  g_ecv[N_EDGES];

// ---------------- helpers ------------------------------------------------------
__device__ __forceinline__ uint2 split2x2(float4 f) { // returns packed hi (4 bf16)
    // helper not used standalone; kept inline below
    return make_uint2(0, 0);
}

__device__ __forceinline__ void split_f4(float4 f, uint2& hi, uint2& lo) {
    __nv_bfloat162 h01 = __floats2bfloat162_rn(f.x, f.y);
    __nv_bfloat162 h23 = __floats2bfloat162_rn(f.z, f.w);
    float2 g01 = __bfloat1622float2(h01);
    float2 g23 = __bfloat1622float2(h23);
    __nv_bfloat162 l01 = __floats2bfloat162_rn(f.x - g01.x, f.y - g01.y);
    __nv_bfloat162 l23 = __floats2bfloat162_rn(f.z - g23.x, f.w - g23.y);
    hi.x = *(uint32_t*)&h01; hi.y = *(uint32_t*)&h23;
    lo.x = *(uint32_t*)&l01; lo.y = *(uint32_t*)&l23;
}

// ---------------- K1: hist + W splits + Y split --------------------------------
__global__ void k_init_all(const int* __restrict__ erow,
                           const float* __restrict__ W1,
                           const float* __restrict__ W2,
                           const float* __restrict__ Y) {
    int b = blockIdx.x;
    if (b < HISTB) {
        int i = b * 256 + threadIdx.x;
        if (i < N_EDGES) atomicAdd(&g_rowptr[erow[i] + 1], 1);
        return;
    }
    b -= HISTB;
    if (b < 256) {               // W1 [256][256] -> T split
        int i = b * 256 + threadIdx.x;
        int r = i >> 8, c = i & 255;
        float v = W1[i];
        __nv_bfloat16 h = __float2bfloat16(v);
        g_W1Th[(size_t)c * D_IN + r] = h;
        g_W1Tl[(size_t)c * D_IN + r] = __float2bfloat16(v - __bfloat162float(h));
        return;
    }
    b -= 256;
    if (b < 128) {               // W2 [256][128] -> T split
        int i = b * 256 + threadIdx.x;
        int r = i >> 7, c = i & 127;
        float v = W2[i];
        __nv_bfloat16 h = __float2bfloat16(v);
        g_W2Th[(size_t)c * D_HID + r] = h;
        g_W2Tl[(size_t)c * D_HID + r] = __float2bfloat16(v - __bfloat162float(h));
        return;
    }
    b -= 128;
    {                            // Y split: 3.2M float4 chunks
        int j = b * 256 + threadIdx.x;
        float4 f = __ldg(((const float4*)Y) + j);
        uint2 hi, lo;
        split_f4(f, hi, lo);
        ((uint2*)g_Yh)[j] = hi;
        ((uint2*)g_Yl)[j] = lo;
    }
}

// ---------------- parallel scan (2 phases) --------------------------------------
__global__ void k_scan1() {
    __shared__ int sh[256];
    int t = threadIdx.x;
    int idx = blockIdx.x * 256 + t;
    int v = (idx < N_NODES + 1) ? g_rowptr[idx] : 0;
    sh[t] = v;
    __syncthreads();
#pragma unroll
    for (int off = 1; off < 256; off <<= 1) {
        int u = (t >= off) ? sh[t - off] : 0;
        __syncthreads();
        sh[t] += u;
        __syncthreads();
    }
    if (idx < N_NODES + 1) g_rowptr[idx] = sh[t];
    if (t == 255) g_bsum[blockIdx.x] = sh[255];
}

__global__ void k_scan3() {
    __shared__ int sh[256];
    int t = threadIdx.x;
    sh[t] = (t < (int)blockIdx.x) ? g_bsum[t] : 0;
    __syncthreads();
#pragma unroll
    for (int off = 128; off > 0; off >>= 1) {
        if (t < off) sh[t] += sh[t + off];
        __syncthreads();
    }
    int offset = sh[0];
    int idx = blockIdx.x * 256 + t;
    if (idx < N_NODES + 1) {
        int v = g_rowptr[idx] + offset;
        g_rowptr[idx] = v;
        if (idx < N_NODES) g_cursor[idx] = v;
    }
}

// ---------------- HMMA GEMM core: bf16 pre-split, cp.async 2-stage --------------
__device__ __forceinline__ void mma_bf16(float* c, const uint32_t* a, const uint32_t* b) {
    asm("mma.sync.aligned.m16n8k16.row.col.f32.bf16.bf16.f32 "
        "{%0,%1,%2,%3}, {%4,%5,%6,%7}, {%8,%9}, {%0,%1,%2,%3};"
        : "+f"(c[0]), "+f"(c[1]), "+f"(c[2]), "+f"(c[3])
        : "r"(a[0]), "r"(a[1]), "r"(a[2]), "r"(a[3]), "r"(b[0]), "r"(b[1]));
}

#define LDSM4(r0, r1, r2, r3, addr)                                            \
    asm volatile("ldmatrix.sync.aligned.m8n8.x4.shared.b16 {%0,%1,%2,%3}, [%4];" \
                 : "=r"(r0), "=r"(r1), "=r"(r2), "=r"(r3) : "r"(addr))
#define CPA16(dst, src, n)                                                     \
    asm volatile("cp.async.cg.shared.global [%0], [%1], 16, %2;"               \
                 :: "r"(dst), "l"(src), "r"(n))
#define CP_COMMIT() asm volatile("cp.async.commit_group;" ::: "memory")
#define CP_WAIT1()  asm volatile("cp.async.wait_group 1;" ::: "memory")
#define CP_WAIT0()  asm volatile("cp.async.wait_group 0;" ::: "memory")

// tile layout per stage (bytes): Ah@0, Al@10240, Bh@20480, Bl@30720; stage=40960
#define STG 40960
#define T_AL 10240
#define T_BH 20480
#define T_BL 30720

__device__ __forceinline__ void gemm_load_stage(
    uint32_t sb, const __nv_bfloat16* __restrict__ Ah,
    const __nv_bfloat16* __restrict__ Al, const __nv_bfloat16* __restrict__ Bh,
    const __nv_bfloat16* __restrict__ Bl, int rowBase, int colBase, int M,
    int k0, int tid)
{
#pragma unroll
    for (int it = 0; it < 2; it++) {
        int ch = tid + it * 256;
        int r = ch >> 2, c = ch & 3;
        uint32_t so = (uint32_t)(r * 80 + c * 16);
        int gr = rowBase + r;
        int ok = (gr < M) ? 16 : 0;
        int grc = (gr < M) ? gr : (M - 1);
        size_t aoff = (size_t)grc * 256 + k0 + c * 8;
        CPA16(sb + so,        Ah + aoff, ok);
        CPA16(sb + T_AL + so, Al + aoff, ok);
        size_t boff = (size_t)(colBase + r) * 256 + k0 + c * 8;
        CPA16(sb + T_BH + so, Bh + boff, 16);
        CPA16(sb + T_BL + so, Bl + boff, 16);
    }
}

__device__ __forceinline__ void gemm_core(
    const __nv_bfloat16* __restrict__ Ah, const __nv_bfloat16* __restrict__ Al,
    const __nv_bfloat16* __restrict__ Bh, const __nv_bfloat16* __restrict__ Bl,
    float* __restrict__ C, int M, int N, int bx, int by)
{
    extern __shared__ __align__(16) char dsm[];
    uint32_t sb = (uint32_t)__cvta_generic_to_shared(dsm);

    int tid = threadIdx.x;
    int lane = tid & 31, wid = tid >> 5;
    int rowBase = by * 128, colBase = bx * 128;
    int wm = (wid >> 2) * 64;
    int wn = (wid & 3) * 32;
    const int SP = 40;

    float acc[4][4][4];
#pragma unroll
    for (int mi = 0; mi < 4; mi++)
#pragma unroll
        for (int ni = 0; ni < 4; ni++)
#pragma unroll
            for (int q = 0; q < 4; q++) acc[mi][ni][q] = 0.f;

    uint32_t aOff[4], bOff[2];
    {
        int ra = ((lane & 8) ? 8 : 0) + (lane & 7);
        int ca = (lane & 16) ? 8 : 0;
#pragma unroll
        for (int mi = 0; mi < 4; mi++)
            aOff[mi] = (uint32_t)(((wm + mi * 16 + ra) * SP + ca) * 2);
        int rb = (lane & 7) + ((lane & 16) ? 8 : 0);
        int cb = (lane & 8) ? 8 : 0;
#pragma unroll
        for (int p = 0; p < 2; p++)
            bOff[p] = (uint32_t)(((wn + p * 16 + rb) * SP + cb) * 2);
    }

    gemm_load_stage(sb, Ah, Al, Bh, Bl, rowBase, colBase, M, 0, tid);
    CP_COMMIT();

    const int KT = 8;
    for (int kt = 0; kt < KT; kt++) {
        uint32_t cur = sb + (uint32_t)(kt & 1) * STG;
        if (kt + 1 < KT) {
            gemm_load_stage(sb + (uint32_t)((kt + 1) & 1) * STG,
                            Ah, Al, Bh, Bl, rowBase, colBase, M,
                            (kt + 1) * 32, tid);
            CP_COMMIT();
            CP_WAIT1();
        } else {
            CP_WAIT0();
        }
        __syncthreads();

#pragma unroll
        for (int ks = 0; ks < 2; ks++) {
            uint32_t kb = (uint32_t)(ks * 32);
            uint32_t bhr[8], blr[8];
            LDSM4(bhr[0], bhr[1], bhr[2], bhr[3], cur + T_BH + bOff[0] + kb);
            LDSM4(bhr[4], bhr[5], bhr[6], bhr[7], cur + T_BH + bOff[1] + kb);
            LDSM4(blr[0], blr[1], blr[2], blr[3], cur + T_BL + bOff[0] + kb);
            LDSM4(blr[4], blr[5], blr[6], blr[7], cur + T_BL + bOff[1] + kb);
#pragma unroll
            for (int mi = 0; mi < 4; mi++) {
                uint32_t ah[4], al[4];
                LDSM4(ah[0], ah[1], ah[2], ah[3], cur + aOff[mi] + kb);
                LDSM4(al[0], al[1], al[2], al[3], cur + T_AL + aOff[mi] + kb);
#pragma unroll
                for (int ni = 0; ni < 4; ni++) {
                    mma_bf16(acc[mi][ni], ah, &bhr[ni * 2]);
                    mma_bf16(acc[mi][ni], ah, &blr[ni * 2]);
                    mma_bf16(acc[mi][ni], al, &bhr[ni * 2]);
                }
            }
        }
        if (kt + 1 < KT) __syncthreads();
    }

#pragma unroll
    for (int mi = 0; mi < 4; mi++) {
        int rr = rowBase + wm + mi * 16 + (lane >> 2);
#pragma unroll
        for (int ni = 0; ni < 4; ni++) {
            int cc = colBase + wn + ni * 8 + (lane & 3) * 2;
            if (rr < M)
                *(float2*)&C[(size_t)rr * N + cc] =
                    make_float2(acc[mi][ni][0], acc[mi][ni][1]);
            if (rr + 8 < M)
                *(float2*)&C[(size_t)(rr + 8) * N + cc] =
                    make_float2(acc[mi][ni][2], acc[mi][ni][3]);
        }
    }
}

// ---------------- fused: GEMM1 blocks + scatter blocks --------------------------
__global__ __launch_bounds__(256, 2)
void k_gemm1_scatter(float* __restrict__ H1,
                     const int* __restrict__ erow, const int* __restrict__ ecol,
                     const float* __restrict__ eval)
{
    if (blockIdx.x < 2 * GRID_M) {
        gemm_core(g_Yh, g_Yl, g_W1Th, g_W1Tl, H1, N_NODES, D_HID,
                  blockIdx.x & 1, blockIdx.x >> 1);
    } else {
        int i = (blockIdx.x - 2 * GRID_M) * 256 + threadIdx.x;
        if (i < N_EDGES) {
            int r = erow[i];
            int p = atomicAdd(&g_cursor[r], 1);
            g_ecv[p] = make_int2(ecol[i], __float_as_int(eval[i]));
        }
    }
}

__global__ __launch_bounds__(256, 2)
void k_gemm2(float* __restrict__ H3)
{
    gemm_core(g_H2h, g_H2l, g_W2Th, g_W2Tl, H3, N_NODES, D_OUT, 0, blockIdx.x);
}

// ---------------- SpMM1: H2{h,l} = split(relu(spmm(H1))) ------------------------
__global__ void k_spmm1(const float* __restrict__ X) {
    int r = blockIdx.x * 4 + threadIdx.y;
    if (r >= N_NODES) return;
    int f4 = threadIdx.x * 4;               // 64 lanes x 4 feats = 256
    int e   = g_rowptr[r];
    int end = g_rowptr[r + 1];
    float4 acc = make_float4(0.f, 0.f, 0.f, 0.f);
    for (; e < end; e++) {
        int2 cv = __ldg(&g_ecv[e]);
        float v = __int_as_float(cv.y);
        float4 x = __ldg((const float4*)&X[(size_t)cv.x * D_HID + f4]);
        acc.x += v * x.x; acc.y += v * x.y; acc.z += v * x.z; acc.w += v * x.w;
    }
    acc.x = fmaxf(acc.x, 0.f); acc.y = fmaxf(acc.y, 0.f);
    acc.z = fmaxf(acc.z, 0.f); acc.w = fmaxf(acc.w, 0.f);
    uint2 hi, lo;
    split_f4(acc, hi, lo);
    *(uint2*)&g_H2h[(size_t)r * D_HID + f4] = hi;
    *(uint2*)&g_H2l[(size_t)r * D_HID + f4] = lo;
}

// ---------------- SpMM2: out = spmm(H3) ------------------------------------------
__global__ void k_spmm2(const float* __restrict__ X, float* __restrict__ out) {
    int r = blockIdx.x * 8 + threadIdx.y;
    if (r >= N_NODES) return;
    int f4 = threadIdx.x * 4;               // 32 lanes x 4 feats = 128
    int e   = g_rowptr[r];
    int end = g_rowptr[r + 1];
    float4 acc = make_float4(0.f, 0.f, 0.f, 0.f);
    for (; e < end; e++) {
        int2 cv = __ldg(&g_ecv[e]);
        float v = __int_as_float(cv.y);
        float4 x = __ldg((const float4*)&X[(size_t)cv.x * D_OUT + f4]);
        acc.x += v * x.x; acc.y += v * x.y; acc.z += v * x.z; acc.w += v * x.w;
    }
    *(float4*)&out[(size_t)r * D_OUT + f4] = acc;
}

// ---------------- launch ----------------------------------------------------------
extern "C" void kernel_launch(void* const* d_in, const int* in_sizes, int n_in,
                              void* d_out, int out_size) {
    const int*   edge_row = (const int*)d_in[1];
    const int*   edge_col = (const int*)d_in[2];
    const float* edge_val = (const float*)d_in[3];
    const float* W1       = (const float*)d_in[4];
    const float* W2       = (const float*)d_in[5];
    const float* Y        = (const float*)d_in[0];
    float*       out      = (float*)d_out;

    float *pH1, *pH3;
    int *pRowptr;
    cudaGetSymbolAddress((void**)&pH1, g_H1);
    cudaGetSymbolAddress((void**)&pH3, g_H3);
    cudaGetSymbolAddress((void**)&pRowptr, g_rowptr);

    const int DSM = 2 * STG;   // 81920 B
    cudaFuncSetAttribute(k_gemm1_scatter,
                         cudaFuncAttributeMaxDynamicSharedMemorySize, DSM);
    cudaFuncSetAttribute(k_gemm2,
                         cudaFuncAttributeMaxDynamicSharedMemorySize, DSM);

    cudaMemsetAsync(pRowptr, 0, (N_NODES + 1) * sizeof(int));
    k_init_all<<<HISTB + 256 + 128 + YSPB, 256>>>(edge_row, W1, W2, Y);
    k_scan1<<<196, 256>>>();
    k_scan3<<<196, 256>>>();
    k_gemm1_scatter<<<2 * GRID_M + HISTB, 256, DSM>>>(pH1, edge_row, edge_col, edge_val);
    {
        dim3 blk(64, 4);
        k_spmm1<<<(N_NODES + 3) / 4, blk>>>(pH1);
    }
    k_gemm2<<<GRID_M, 256, DSM>>>(pH3);
    {
        dim3 blk(32, 8);
        k_spmm2<<<(N_NODES + 7) / 8, blk>>>(pH3, out);
    }
}

// round 8
// speedup vs baseline: 1.4955x; 1.0108x over previous
#include <cuda_runtime.h>
#include <cuda_bf16.h>
#include <cstdint>

#define N_NODES 50000
#define N_EDGES 800000
#define D_IN    256
#define D_HID   256
#define D_OUT   128
#define GRID_M  391            // ceil(50000/128)
#define HISTB   3125           // ceil(800000/256)
#define YSPB    12500          // 50000*256/4 float4 / 256 threads
#define G1B     (2 * GRID_M)   // 782 GEMM1 blocks
#define EPB     1024           // edges scattered per GEMM1 block

// ---------------- scratch ------------------------------------------------------
__device__ float g_H1[(size_t)N_NODES * D_HID];
__device__ __nv_bfloat16 g_H2h[(size_t)N_NODES * D_HID];
__device__ __nv_bfloat16 g_H2l[(size_t)N_NODES * D_HID];
__device__ float g_H3[(size_t)N_NODES * D_OUT];
__device__ __nv_bfloat16 g_Yh[(size_t)N_NODES * D_IN];
__device__ __nv_bfloat16 g_Yl[(size_t)N_NODES * D_IN];
__device__ __nv_bfloat16 g_W1Th[D_HID * D_IN];
__device__ __nv_bfloat16 g_W1Tl[D_HID * D_IN];
__device__ __nv_bfloat16 g_W2Th[D_OUT * D_HID];
__device__ __nv_bfloat16 g_W2Tl[D_OUT * D_HID];
__device__ int   g_rowptr[N_NODES + 1];
__device__ int   g_cursor[N_NODES];
__device__ int   g_bsum[256];
__device__ int2  g_ecv[N_EDGES];

// ---------------- helpers ------------------------------------------------------
__device__ __forceinline__ void split_f4(float4 f, uint2& hi, uint2& lo) {
    __nv_bfloat162 h01 = __floats2bfloat162_rn(f.x, f.y);
    __nv_bfloat162 h23 = __floats2bfloat162_rn(f.z, f.w);
    float2 g01 = __bfloat1622float2(h01);
    float2 g23 = __bfloat1622float2(h23);
    __nv_bfloat162 l01 = __floats2bfloat162_rn(f.x - g01.x, f.y - g01.y);
    __nv_bfloat162 l23 = __floats2bfloat162_rn(f.z - g23.x, f.w - g23.y);
    hi.x = *(uint32_t*)&h01; hi.y = *(uint32_t*)&h23;
    lo.x = *(uint32_t*)&l01; lo.y = *(uint32_t*)&l23;
}

// ---------------- K1: hist + W splits + Y split --------------------------------
__global__ void k_init_all(const int* __restrict__ erow,
                           const float* __restrict__ W1,
                           const float* __restrict__ W2,
                           const float* __restrict__ Y) {
    int b = blockIdx.x;
    if (b < HISTB) {
        int i = b * 256 + threadIdx.x;
        if (i < N_EDGES) atomicAdd(&g_rowptr[erow[i] + 1], 1);
        return;
    }
    b -= HISTB;
    if (b < 256) {               // W1 [256][256] -> T split
        int i = b * 256 + threadIdx.x;
        int r = i >> 8, c = i & 255;
        float v = W1[i];
        __nv_bfloat16 h = __float2bfloat16(v);
        g_W1Th[(size_t)c * D_IN + r] = h;
        g_W1Tl[(size_t)c * D_IN + r] = __float2bfloat16(v - __bfloat162float(h));
        return;
    }
    b -= 256;
    if (b < 128) {               // W2 [256][128] -> T split
        int i = b * 256 + threadIdx.x;
        int r = i >> 7, c = i & 127;
        float v = W2[i];
        __nv_bfloat16 h = __float2bfloat16(v);
        g_W2Th[(size_t)c * D_HID + r] = h;
        g_W2Tl[(size_t)c * D_HID + r] = __float2bfloat16(v - __bfloat162float(h));
        return;
    }
    b -= 128;
    {                            // Y split: 3.2M float4 chunks
        int j = b * 256 + threadIdx.x;
        float4 f = __ldg(((const float4*)Y) + j);
        uint2 hi, lo;
        split_f4(f, hi, lo);
        ((uint2*)g_Yh)[j] = hi;
        ((uint2*)g_Yl)[j] = lo;
    }
}

// ---------------- parallel scan (2 phases) --------------------------------------
__global__ void k_scan1() {
    __shared__ int sh[256];
    int t = threadIdx.x;
    int idx = blockIdx.x * 256 + t;
    int v = (idx < N_NODES + 1) ? g_rowptr[idx] : 0;
    sh[t] = v;
    __syncthreads();
#pragma unroll
    for (int off = 1; off < 256; off <<= 1) {
        int u = (t >= off) ? sh[t - off] : 0;
        __syncthreads();
        sh[t] += u;
        __syncthreads();
    }
    if (idx < N_NODES + 1) g_rowptr[idx] = sh[t];
    if (t == 255) g_bsum[blockIdx.x] = sh[255];
}

__global__ void k_scan3() {
    __shared__ int sh[256];
    int t = threadIdx.x;
    sh[t] = (t < (int)blockIdx.x) ? g_bsum[t] : 0;
    __syncthreads();
#pragma unroll
    for (int off = 128; off > 0; off >>= 1) {
        if (t < off) sh[t] += sh[t + off];
        __syncthreads();
    }
    int offset = sh[0];
    int idx = blockIdx.x * 256 + t;
    if (idx < N_NODES + 1) {
        int v = g_rowptr[idx] + offset;
        g_rowptr[idx] = v;
        if (idx < N_NODES) g_cursor[idx] = v;
    }
}

// ---------------- HMMA GEMM core: bf16 pre-split, cp.async 2-stage --------------
__device__ __forceinline__ void mma_bf16(float* c, const uint32_t* a, const uint32_t* b) {
    asm("mma.sync.aligned.m16n8k16.row.col.f32.bf16.bf16.f32 "
        "{%0,%1,%2,%3}, {%4,%5,%6,%7}, {%8,%9}, {%0,%1,%2,%3};"
        : "+f"(c[0]), "+f"(c[1]), "+f"(c[2]), "+f"(c[3])
        : "r"(a[0]), "r"(a[1]), "r"(a[2]), "r"(a[3]), "r"(b[0]), "r"(b[1]));
}

#define LDSM4(r0, r1, r2, r3, addr)                                            \
    asm volatile("ldmatrix.sync.aligned.m8n8.x4.shared.b16 {%0,%1,%2,%3}, [%4];" \
                 : "=r"(r0), "=r"(r1), "=r"(r2), "=r"(r3) : "r"(addr))
#define CPA16(dst, src, n)                                                     \
    asm volatile("cp.async.cg.shared.global [%0], [%1], 16, %2;"               \
                 :: "r"(dst), "l"(src), "r"(n))
#define CP_COMMIT() asm volatile("cp.async.commit_group;" ::: "memory")
#define CP_WAIT1()  asm volatile("cp.async.wait_group 1;" ::: "memory")
#define CP_WAIT0()  asm volatile("cp.async.wait_group 0;" ::: "memory")

// tile layout per stage (bytes): Ah@0, Al@10240, Bh@20480, Bl@30720; stage=40960
#define STG 40960
#define T_AL 10240
#define T_BH 20480
#define T_BL 30720

__device__ __forceinline__ void gemm_load_stage(
    uint32_t sb, const __nv_bfloat16* __restrict__ Ah,
    const __nv_bfloat16* __restrict__ Al, const __nv_bfloat16* __restrict__ Bh,
    const __nv_bfloat16* __restrict__ Bl, int rowBase, int colBase, int M,
    int k0, int tid)
{
#pragma unroll
    for (int it = 0; it < 2; it++) {
        int ch = tid + it * 256;
        int r = ch >> 2, c = ch & 3;
        uint32_t so = (uint32_t)(r * 80 + c * 16);
        int gr = rowBase + r;
        int ok = (gr < M) ? 16 : 0;
        int grc = (gr < M) ? gr : (M - 1);
        size_t aoff = (size_t)grc * 256 + k0 + c * 8;
        CPA16(sb + so,        Ah + aoff, ok);
        CPA16(sb + T_AL + so, Al + aoff, ok);
        size_t boff = (size_t)(colBase + r) * 256 + k0 + c * 8;
        CPA16(sb + T_BH + so, Bh + boff, 16);
        CPA16(sb + T_BL + so, Bl + boff, 16);
    }
}

__device__ __forceinline__ void gemm_core(
    const __nv_bfloat16* __restrict__ Ah, const __nv_bfloat16* __restrict__ Al,
    const __nv_bfloat16* __restrict__ Bh, const __nv_bfloat16* __restrict__ Bl,
    float* __restrict__ C, int M, int N, int bx, int by)
{
    extern __shared__ __align__(16) char dsm[];
    uint32_t sb = (uint32_t)__cvta_generic_to_shared(dsm);

    int tid = threadIdx.x;
    int lane = tid & 31, wid = tid >> 5;
    int rowBase = by * 128, colBase = bx * 128;
    int wm = (wid >> 2) * 64;
    int wn = (wid & 3) * 32;
    const int SP = 40;

    float acc[4][4][4];
#pragma unroll
    for (int mi = 0; mi < 4; mi++)
#pragma unroll
        for (int ni = 0; ni < 4; ni++)
#pragma unroll
            for (int q = 0; q < 4; q++) acc[mi][ni][q] = 0.f;

    uint32_t aOff[4], bOff[2];
    {
        int ra = ((lane & 8) ? 8 : 0) + (lane & 7);
        int ca = (lane & 16) ? 8 : 0;
#pragma unroll
        for (int mi = 0; mi < 4; mi++)
            aOff[mi] = (uint32_t)(((wm + mi * 16 + ra) * SP + ca) * 2);
        int rb = (lane & 7) + ((lane & 16) ? 8 : 0);
        int cb = (lane & 8) ? 8 : 0;
#pragma unroll
        for (int p = 0; p < 2; p++)
            bOff[p] = (uint32_t)(((wn + p * 16 + rb) * SP + cb) * 2);
    }

    gemm_load_stage(sb, Ah, Al, Bh, Bl, rowBase, colBase, M, 0, tid);
    CP_COMMIT();

    const int KT = 8;
    for (int kt = 0; kt < KT; kt++) {
        uint32_t cur = sb + (uint32_t)(kt & 1) * STG;
        if (kt + 1 < KT) {
            gemm_load_stage(sb + (uint32_t)((kt + 1) & 1) * STG,
                            Ah, Al, Bh, Bl, rowBase, colBase, M,
                            (kt + 1) * 32, tid);
            CP_COMMIT();
            CP_WAIT1();
        } else {
            CP_WAIT0();
        }
        __syncthreads();

#pragma unroll
        for (int ks = 0; ks < 2; ks++) {
            uint32_t kb = (uint32_t)(ks * 32);
            uint32_t bhr[8], blr[8];
            LDSM4(bhr[0], bhr[1], bhr[2], bhr[3], cur + T_BH + bOff[0] + kb);
            LDSM4(bhr[4], bhr[5], bhr[6], bhr[7], cur + T_BH + bOff[1] + kb);
            LDSM4(blr[0], blr[1], blr[2], blr[3], cur + T_BL + bOff[0] + kb);
            LDSM4(blr[4], blr[5], blr[6], blr[7], cur + T_BL + bOff[1] + kb);
#pragma unroll
            for (int mi = 0; mi < 4; mi++) {
                uint32_t ah[4], al[4];
                LDSM4(ah[0], ah[1], ah[2], ah[3], cur + aOff[mi] + kb);
                LDSM4(al[0], al[1], al[2], al[3], cur + T_AL + aOff[mi] + kb);
#pragma unroll
                for (int ni = 0; ni < 4; ni++) {
                    mma_bf16(acc[mi][ni], ah, &bhr[ni * 2]);
                    mma_bf16(acc[mi][ni], ah, &blr[ni * 2]);
                    mma_bf16(acc[mi][ni], al, &bhr[ni * 2]);
                }
            }
        }
        if (kt + 1 < KT) __syncthreads();
    }

#pragma unroll
    for (int mi = 0; mi < 4; mi++) {
        int rr = rowBase + wm + mi * 16 + (lane >> 2);
#pragma unroll
        for (int ni = 0; ni < 4; ni++) {
            int cc = colBase + wn + ni * 8 + (lane & 3) * 2;
            if (rr < M)
                *(float2*)&C[(size_t)rr * N + cc] =
                    make_float2(acc[mi][ni][0], acc[mi][ni][1]);
            if (rr + 8 < M)
                *(float2*)&C[(size_t)(rr + 8) * N + cc] =
                    make_float2(acc[mi][ni][2], acc[mi][ni][3]);
        }
    }
}

// ---------------- GEMM1 with scatter slice appended to each block ---------------
__global__ __launch_bounds__(256, 2)
void k_gemm1_scatter(float* __restrict__ H1,
                     const int* __restrict__ erow, const int* __restrict__ ecol,
                     const float* __restrict__ eval)
{
    gemm_core(g_Yh, g_Yl, g_W1Th, g_W1Tl, H1, N_NODES, D_HID,
              blockIdx.x & 1, blockIdx.x >> 1);
    // scatter slice: EPB edges per block, appended after tile compute
    int base = blockIdx.x * EPB + threadIdx.x;
#pragma unroll
    for (int q = 0; q < EPB / 256; q++) {
        int i = base + q * 256;
        if (i < N_EDGES) {
            int r = erow[i];
            int p = atomicAdd(&g_cursor[r], 1);
            g_ecv[p] = make_int2(ecol[i], __float_as_int(eval[i]));
        }
    }
}

__global__ __launch_bounds__(256, 2)
void k_gemm2(float* __restrict__ H3)
{
    gemm_core(g_H2h, g_H2l, g_W2Th, g_W2Tl, H3, N_NODES, D_OUT, 0, blockIdx.x);
}

// ---------------- SpMM1: H2{h,l} = split(relu(spmm(H1))), 4-wide unrolled -------
__global__ void k_spmm1(const float* __restrict__ X) {
    int r = blockIdx.x * 4 + threadIdx.y;
    if (r >= N_NODES) return;
    int f4 = threadIdx.x * 4;               // 64 lanes x 4 feats = 256
    int e   = g_rowptr[r];
    int end = g_rowptr[r + 1];
    float4 acc = make_float4(0.f, 0.f, 0.f, 0.f);
    for (; e + 4 <= end; e += 4) {
        int2 cv0 = __ldg(&g_ecv[e]);
        int2 cv1 = __ldg(&g_ecv[e + 1]);
        int2 cv2 = __ldg(&g_ecv[e + 2]);
        int2 cv3 = __ldg(&g_ecv[e + 3]);
        float4 x0 = __ldg((const float4*)&X[(size_t)cv0.x * D_HID + f4]);
        float4 x1 = __ldg((const float4*)&X[(size_t)cv1.x * D_HID + f4]);
        float4 x2 = __ldg((const float4*)&X[(size_t)cv2.x * D_HID + f4]);
        float4 x3 = __ldg((const float4*)&X[(size_t)cv3.x * D_HID + f4]);
        float v0 = __int_as_float(cv0.y), v1 = __int_as_float(cv1.y);
        float v2 = __int_as_float(cv2.y), v3 = __int_as_float(cv3.y);
        acc.x += v0 * x0.x; acc.y += v0 * x0.y; acc.z += v0 * x0.z; acc.w += v0 * x0.w;
        acc.x += v1 * x1.x; acc.y += v1 * x1.y; acc.z += v1 * x1.z; acc.w += v1 * x1.w;
        acc.x += v2 * x2.x; acc.y += v2 * x2.y; acc.z += v2 * x2.z; acc.w += v2 * x2.w;
        acc.x += v3 * x3.x; acc.y += v3 * x3.y; acc.z += v3 * x3.z; acc.w += v3 * x3.w;
    }
    for (; e < end; e++) {
        int2 cv = __ldg(&g_ecv[e]);
        float v = __int_as_float(cv.y);
        float4 x = __ldg((const float4*)&X[(size_t)cv.x * D_HID + f4]);
        acc.x += v * x.x; acc.y += v * x.y; acc.z += v * x.z; acc.w += v * x.w;
    }
    acc.x = fmaxf(acc.x, 0.f); acc.y = fmaxf(acc.y, 0.f);
    acc.z = fmaxf(acc.z, 0.f); acc.w = fmaxf(acc.w, 0.f);
    uint2 hi, lo;
    split_f4(acc, hi, lo);
    *(uint2*)&g_H2h[(size_t)r * D_HID + f4] = hi;
    *(uint2*)&g_H2l[(size_t)r * D_HID + f4] = lo;
}

// ---------------- SpMM2: out = spmm(H3), 4-wide unrolled -------------------------
__global__ void k_spmm2(const float* __restrict__ X, float* __restrict__ out) {
    int r = blockIdx.x * 8 + threadIdx.y;
    if (r >= N_NODES) return;
    int f4 = threadIdx.x * 4;               // 32 lanes x 4 feats = 128
    int e   = g_rowptr[r];
    int end = g_rowptr[r + 1];
    float4 acc = make_float4(0.f, 0.f, 0.f, 0.f);
    for (; e + 4 <= end; e += 4) {
        int2 cv0 = __ldg(&g_ecv[e]);
        int2 cv1 = __ldg(&g_ecv[e + 1]);
        int2 cv2 = __ldg(&g_ecv[e + 2]);
        int2 cv3 = __ldg(&g_ecv[e + 3]);
        float4 x0 = __ldg((const float4*)&X[(size_t)cv0.x * D_OUT + f4]);
        float4 x1 = __ldg((const float4*)&X[(size_t)cv1.x * D_OUT + f4]);
        float4 x2 = __ldg((const float4*)&X[(size_t)cv2.x * D_OUT + f4]);
        float4 x3 = __ldg((const float4*)&X[(size_t)cv3.x * D_OUT + f4]);
        float v0 = __int_as_float(cv0.y), v1 = __int_as_float(cv1.y);
        float v2 = __int_as_float(cv2.y), v3 = __int_as_float(cv3.y);
        acc.x += v0 * x0.x; acc.y += v0 * x0.y; acc.z += v0 * x0.z; acc.w += v0 * x0.w;
        acc.x += v1 * x1.x; acc.y += v1 * x1.y; acc.z += v1 * x1.z; acc.w += v1 * x1.w;
        acc.x += v2 * x2.x; acc.y += v2 * x2.y; acc.z += v2 * x2.z; acc.w += v2 * x2.w;
        acc.x += v3 * x3.x; acc.y += v3 * x3.y; acc.z += v3 * x3.z; acc.w += v3 * x3.w;
    }
    for (; e < end; e++) {
        int2 cv = __ldg(&g_ecv[e]);
        float v = __int_as_float(cv.y);
        float4 x = __ldg((const float4*)&X[(size_t)cv.x * D_OUT + f4]);
        acc.x += v * x.x; acc.y += v * x.y; acc.z += v * x.z; acc.w += v * x.w;
    }
    *(float4*)&out[(size_t)r * D_OUT + f4] = acc;
}

// ---------------- launch ----------------------------------------------------------
extern "C" void kernel_launch(void* const* d_in, const int* in_sizes, int n_in,
                              void* d_out, int out_size) {
    const float* Y        = (const float*)d_in[0];
    const int*   edge_row = (const int*)d_in[1];
    const int*   edge_col = (const int*)d_in[2];
    const float* edge_val = (const float*)d_in[3];
    const float* W1       = (const float*)d_in[4];
    const float* W2       = (const float*)d_in[5];
    float*       out      = (float*)d_out;

    float *pH1, *pH3;
    int *pRowptr;
    cudaGetSymbolAddress((void**)&pH1, g_H1);
    cudaGetSymbolAddress((void**)&pH3, g_H3);
    cudaGetSymbolAddress((void**)&pRowptr, g_rowptr);

    const int DSM = 2 * STG;   // 81920 B
    cudaFuncSetAttribute(k_gemm1_scatter,
                         cudaFuncAttributeMaxDynamicSharedMemorySize, DSM);
    cudaFuncSetAttribute(k_gemm2,
                         cudaFuncAttributeMaxDynamicSharedMemorySize, DSM);

    cudaMemsetAsync(pRowptr, 0, (N_NODES + 1) * sizeof(int));
    k_init_all<<<HISTB + 256 + 128 + YSPB, 256>>>(edge_row, W1, W2, Y);
    k_scan1<<<196, 256>>>();
    k_scan3<<<196, 256>>>();
    k_gemm1_scatter<<<G1B, 256, DSM>>>(pH1, edge_row, edge_col, edge_val);
    {
        dim3 blk(64, 4);
        k_spmm1<<<(N_NODES + 3) / 4, blk>>>(pH1);
    }
    k_gemm2<<<GRID_M, 256, DSM>>>(pH3);
    {
        dim3 blk(32, 8);
        k_spmm2<<<(N_NODES + 7) / 8, blk>>>(pH3, out);
    }
}

// round 9
// speedup vs baseline: 1.5623x; 1.0447x over previous
#include <cuda_runtime.h>
#include <cuda_bf16.h>
#include <cstdint>

#define N_NODES 50000
#define N_EDGES 800000
#define D_IN    256
#define D_HID   256
#define D_OUT   128
#define GRID_M  391            // ceil(50000/128)
#define HISTB   3125           // ceil(800000/256)
#define YSPB    12500          // 50000*256/4 float4 / 256 threads
#define G1B     (2 * GRID_M)   // 782 GEMM1 blocks
#define EPB     1024           // edges scattered per GEMM1 block

// ---------------- scratch ------------------------------------------------------
__device__ float g_H1[(size_t)N_NODES * D_HID];
__device__ __nv_bfloat16 g_H2h[(size_t)N_NODES * D_HID];
__device__ __nv_bfloat16 g_H2l[(size_t)N_NODES * D_HID];
__device__ float g_H3[(size_t)N_NODES * D_OUT];
__device__ __nv_bfloat16 g_Yh[(size_t)N_NODES * D_IN];
__device__ __nv_bfloat16 g_Yl[(size_t)N_NODES * D_IN];
__device__ __nv_bfloat16 g_W1Th[D_HID * D_IN];
__device__ __nv_bfloat16 g_W1Tl[D_HID * D_IN];
__device__ __nv_bfloat16 g_W2Th[D_OUT * D_HID];
__device__ __nv_bfloat16 g_W2Tl[D_OUT * D_HID];
__device__ int   g_rowptr[N_NODES + 1];
__device__ int   g_cursor[N_NODES];
__device__ int   g_bsum[256];
__device__ int2  g_ecv[N_EDGES];

// ---------------- helpers ------------------------------------------------------
__device__ __forceinline__ void split_f4(float4 f, uint2& hi, uint2& lo) {
    __nv_bfloat162 h01 = __floats2bfloat162_rn(f.x, f.y);
    __nv_bfloat162 h23 = __floats2bfloat162_rn(f.z, f.w);
    float2 g01 = __bfloat1622float2(h01);
    float2 g23 = __bfloat1622float2(h23);
    __nv_bfloat162 l01 = __floats2bfloat162_rn(f.x - g01.x, f.y - g01.y);
    __nv_bfloat162 l23 = __floats2bfloat162_rn(f.z - g23.x, f.w - g23.y);
    hi.x = *(uint32_t*)&h01; hi.y = *(uint32_t*)&h23;
    lo.x = *(uint32_t*)&l01; lo.y = *(uint32_t*)&l23;
}

// ---------------- K1: hist + W splits + Y split --------------------------------
__global__ void k_init_all(const int* __restrict__ erow,
                           const float* __restrict__ W1,
                           const float* __restrict__ W2,
                           const float* __restrict__ Y) {
    int b = blockIdx.x;
    if (b < HISTB) {
        int i = b * 256 + threadIdx.x;
        if (i < N_EDGES) atomicAdd(&g_rowptr[erow[i] + 1], 1);
        return;
    }
    b -= HISTB;
    if (b < 256) {               // W1 [256][256] -> T split
        int i = b * 256 + threadIdx.x;
        int r = i >> 8, c = i & 255;
        float v = W1[i];
        __nv_bfloat16 h = __float2bfloat16(v);
        g_W1Th[(size_t)c * D_IN + r] = h;
        g_W1Tl[(size_t)c * D_IN + r] = __float2bfloat16(v - __bfloat162float(h));
        return;
    }
    b -= 256;
    if (b < 128) {               // W2 [256][128] -> T split
        int i = b * 256 + threadIdx.x;
        int r = i >> 7, c = i & 127;
        float v = W2[i];
        __nv_bfloat16 h = __float2bfloat16(v);
        g_W2Th[(size_t)c * D_HID + r] = h;
        g_W2Tl[(size_t)c * D_HID + r] = __float2bfloat16(v - __bfloat162float(h));
        return;
    }
    b -= 128;
    {                            // Y split: 3.2M float4 chunks
        int j = b * 256 + threadIdx.x;
        float4 f = __ldg(((const float4*)Y) + j);
        uint2 hi, lo;
        split_f4(f, hi, lo);
        ((uint2*)g_Yh)[j] = hi;
        ((uint2*)g_Yl)[j] = lo;
    }
}

// ---------------- parallel scan (2 phases) --------------------------------------
__global__ void k_scan1() {
    __shared__ int sh[256];
    int t = threadIdx.x;
    int idx = blockIdx.x * 256 + t;
    int v = (idx < N_NODES + 1) ? g_rowptr[idx] : 0;
    sh[t] = v;
    __syncthreads();
#pragma unroll
    for (int off = 1; off < 256; off <<= 1) {
        int u = (t >= off) ? sh[t - off] : 0;
        __syncthreads();
        sh[t] += u;
        __syncthreads();
    }
    if (idx < N_NODES + 1) g_rowptr[idx] = sh[t];
    if (t == 255) g_bsum[blockIdx.x] = sh[255];
}

__global__ void k_scan3() {
    __shared__ int sh[256];
    int t = threadIdx.x;
    sh[t] = (t < (int)blockIdx.x) ? g_bsum[t] : 0;
    __syncthreads();
#pragma unroll
    for (int off = 128; off > 0; off >>= 1) {
        if (t < off) sh[t] += sh[t + off];
        __syncthreads();
    }
    int offset = sh[0];
    int idx = blockIdx.x * 256 + t;
    if (idx < N_NODES + 1) {
        int v = g_rowptr[idx] + offset;
        g_rowptr[idx] = v;
        if (idx < N_NODES) g_cursor[idx] = v;
    }
}

// ---------------- HMMA GEMM core: swizzled smem, cp.async 3-stage ---------------
__device__ __forceinline__ void mma_bf16(float* c, const uint32_t* a, const uint32_t* b) {
    asm("mma.sync.aligned.m16n8k16.row.col.f32.bf16.bf16.f32 "
        "{%0,%1,%2,%3}, {%4,%5,%6,%7}, {%8,%9}, {%0,%1,%2,%3};"
        : "+f"(c[0]), "+f"(c[1]), "+f"(c[2]), "+f"(c[3])
        : "r"(a[0]), "r"(a[1]), "r"(a[2]), "r"(a[3]), "r"(b[0]), "r"(b[1]));
}

#define LDSM4(r0, r1, r2, r3, addr)                                            \
    asm volatile("ldmatrix.sync.aligned.m8n8.x4.shared.b16 {%0,%1,%2,%3}, [%4];" \
                 : "=r"(r0), "=r"(r1), "=r"(r2), "=r"(r3) : "r"(addr))
#define CPA16(dst, src, n)                                                     \
    asm volatile("cp.async.cg.shared.global [%0], [%1], 16, %2;"               \
                 :: "r"(dst), "l"(src), "r"(n))
#define CP_COMMIT() asm volatile("cp.async.commit_group;" ::: "memory")
#define CP_WAIT2()  asm volatile("cp.async.wait_group 2;" ::: "memory")
#define CP_WAIT1()  asm volatile("cp.async.wait_group 1;" ::: "memory")
#define CP_WAIT0()  asm volatile("cp.async.wait_group 0;" ::: "memory")

// stage layout (bytes): Ah@0, Al@8192, Bh@16384, Bl@24576; stage=32768.
// 64B rows (32 bf16); chunk swizzle: phys16B = c ^ ((r>>1)&3)
#define STG  32768
#define T_AL 8192
#define T_BH 16384
#define T_BL 24576
#define NSTG 3

__device__ __forceinline__ void gemm_load_stage(
    uint32_t sb, const __nv_bfloat16* __restrict__ Ah,
    const __nv_bfloat16* __restrict__ Al, const __nv_bfloat16* __restrict__ Bh,
    const __nv_bfloat16* __restrict__ Bl, int rowBase, int colBase, int M,
    int k0, int tid)
{
#pragma unroll
    for (int it = 0; it < 2; it++) {
        int ch = tid + it * 256;
        int r = ch >> 2, c = ch & 3;
        uint32_t so = (uint32_t)(r * 64 + ((c ^ ((r >> 1) & 3)) * 16));
        int gr = rowBase + r;
        int ok = (gr < M) ? 16 : 0;
        int grc = (gr < M) ? gr : (M - 1);
        size_t aoff = (size_t)grc * 256 + k0 + c * 8;
        CPA16(sb + so,        Ah + aoff, ok);
        CPA16(sb + T_AL + so, Al + aoff, ok);
        size_t boff = (size_t)(colBase + r) * 256 + k0 + c * 8;
        CPA16(sb + T_BH + so, Bh + boff, 16);
        CPA16(sb + T_BL + so, Bl + boff, 16);
    }
}

__device__ __forceinline__ void gemm_core(
    const __nv_bfloat16* __restrict__ Ah, const __nv_bfloat16* __restrict__ Al,
    const __nv_bfloat16* __restrict__ Bh, const __nv_bfloat16* __restrict__ Bl,
    float* __restrict__ C, int M, int N, int bx, int by)
{
    extern __shared__ __align__(128) char dsm[];
    uint32_t sb = (uint32_t)__cvta_generic_to_shared(dsm);

    int tid = threadIdx.x;
    int lane = tid & 31, wid = tid >> 5;
    int rowBase = by * 128, colBase = bx * 128;
    int wm = (wid >> 2) * 64;
    int wn = (wid & 3) * 32;

    float acc[4][4][4];
#pragma unroll
    for (int mi = 0; mi < 4; mi++)
#pragma unroll
        for (int ni = 0; ni < 4; ni++)
#pragma unroll
            for (int q = 0; q < 4; q++) acc[mi][ni][q] = 0.f;

    // per-lane fragment row bases + swizzle keys
    uint32_t aRow[4], aS[4], bRow[2], bS[2];
    uint32_t kaBase = (lane & 16) ? 16u : 0u;   // A chunk-byte base within row
    uint32_t kbBase = (lane & 8) ? 16u : 0u;    // B chunk-byte base within row
    {
        int ra = (lane & 7) + ((lane & 8) ? 8 : 0);
#pragma unroll
        for (int mi = 0; mi < 4; mi++) {
            int r = wm + mi * 16 + ra;
            aRow[mi] = (uint32_t)(r * 64);
            aS[mi]   = (uint32_t)(((r >> 1) & 3) * 16);
        }
        int rb = (lane & 7) + ((lane & 16) ? 8 : 0);
#pragma unroll
        for (int p = 0; p < 2; p++) {
            int r = wn + p * 16 + rb;
            bRow[p] = (uint32_t)(r * 64);
            bS[p]   = (uint32_t)(((r >> 1) & 3) * 16);
        }
    }

    gemm_load_stage(sb, Ah, Al, Bh, Bl, rowBase, colBase, M, 0, tid);
    CP_COMMIT();
    gemm_load_stage(sb + STG, Ah, Al, Bh, Bl, rowBase, colBase, M, 32, tid);
    CP_COMMIT();

    const int KT = 8;
    for (int kt = 0; kt < KT; kt++) {
        uint32_t cur = sb + (uint32_t)(kt % NSTG) * STG;
        if (kt < KT - 2) {
            gemm_load_stage(sb + (uint32_t)((kt + 2) % NSTG) * STG,
                            Ah, Al, Bh, Bl, rowBase, colBase, M,
                            (kt + 2) * 32, tid);
            CP_COMMIT();
            CP_WAIT2();
        } else if (kt == KT - 2) {
            CP_WAIT1();
        } else {
            CP_WAIT0();
        }
        __syncthreads();

#pragma unroll
        for (int ks = 0; ks < 2; ks++) {
            uint32_t kA = (uint32_t)(ks * 32) + kaBase;
            uint32_t kB = (uint32_t)(ks * 32) + kbBase;
            uint32_t bhr[8], blr[8];
            LDSM4(bhr[0], bhr[1], bhr[2], bhr[3],
                  cur + T_BH + bRow[0] + (kB ^ bS[0]));
            LDSM4(bhr[4], bhr[5], bhr[6], bhr[7],
                  cur + T_BH + bRow[1] + (kB ^ bS[1]));
            LDSM4(blr[0], blr[1], blr[2], blr[3],
                  cur + T_BL + bRow[0] + (kB ^ bS[0]));
            LDSM4(blr[4], blr[5], blr[6], blr[7],
                  cur + T_BL + bRow[1] + (kB ^ bS[1]));
#pragma unroll
            for (int mi = 0; mi < 4; mi++) {
                uint32_t ah[4], al[4];
                LDSM4(ah[0], ah[1], ah[2], ah[3],
                      cur + aRow[mi] + (kA ^ aS[mi]));
                LDSM4(al[0], al[1], al[2], al[3],
                      cur + T_AL + aRow[mi] + (kA ^ aS[mi]));
#pragma unroll
                for (int ni = 0; ni < 4; ni++) {
                    mma_bf16(acc[mi][ni], ah, &bhr[ni * 2]);
                    mma_bf16(acc[mi][ni], ah, &blr[ni * 2]);
                    mma_bf16(acc[mi][ni], al, &bhr[ni * 2]);
                }
            }
        }
        if (kt + 1 < KT) __syncthreads();
    }

#pragma unroll
    for (int mi = 0; mi < 4; mi++) {
        int rr = rowBase + wm + mi * 16 + (lane >> 2);
#pragma unroll
        for (int ni = 0; ni < 4; ni++) {
            int cc = colBase + wn + ni * 8 + (lane & 3) * 2;
            if (rr < M)
                *(float2*)&C[(size_t)rr * N + cc] =
                    make_float2(acc[mi][ni][0], acc[mi][ni][1]);
            if (rr + 8 < M)
                *(float2*)&C[(size_t)(rr + 8) * N + cc] =
                    make_float2(acc[mi][ni][2], acc[mi][ni][3]);
        }
    }
}

// ---------------- GEMM1 with scatter slice appended ------------------------------
__global__ __launch_bounds__(256, 2)
void k_gemm1_scatter(float* __restrict__ H1,
                     const int* __restrict__ erow, const int* __restrict__ ecol,
                     const float* __restrict__ eval)
{
    gemm_core(g_Yh, g_Yl, g_W1Th, g_W1Tl, H1, N_NODES, D_HID,
              blockIdx.x & 1, blockIdx.x >> 1);
    int base = blockIdx.x * EPB + threadIdx.x;
#pragma unroll
    for (int q = 0; q < EPB / 256; q++) {
        int i = base + q * 256;
        if (i < N_EDGES) {
            int r = erow[i];
            int p = atomicAdd(&g_cursor[r], 1);
            g_ecv[p] = make_int2(ecol[i], __float_as_int(eval[i]));
        }
    }
}

__global__ __launch_bounds__(256, 2)
void k_gemm2(float* __restrict__ H3)
{
    gemm_core(g_H2h, g_H2l, g_W2Th, g_W2Tl, H3, N_NODES, D_OUT, 0, blockIdx.x);
}

// ---------------- SpMM1: H2{h,l} = split(relu(spmm(H1))), 4-wide unrolled --------
__global__ void k_spmm1(const float* __restrict__ X) {
    int r = blockIdx.x * 4 + threadIdx.y;
    if (r >= N_NODES) return;
    int f4 = threadIdx.x * 4;               // 64 lanes x 4 feats = 256
    int e   = g_rowptr[r];
    int end = g_rowptr[r + 1];
    float4 acc = make_float4(0.f, 0.f, 0.f, 0.f);
    for (; e + 4 <= end; e += 4) {
        int2 cv0 = __ldg(&g_ecv[e]);
        int2 cv1 = __ldg(&g_ecv[e + 1]);
        int2 cv2 = __ldg(&g_ecv[e + 2]);
        int2 cv3 = __ldg(&g_ecv[e + 3]);
        float4 x0 = __ldg((const float4*)&X[(size_t)cv0.x * D_HID + f4]);
        float4 x1 = __ldg((const float4*)&X[(size_t)cv1.x * D_HID + f4]);
        float4 x2 = __ldg((const float4*)&X[(size_t)cv2.x * D_HID + f4]);
        float4 x3 = __ldg((const float4*)&X[(size_t)cv3.x * D_HID + f4]);
        float v0 = __int_as_float(cv0.y), v1 = __int_as_float(cv1.y);
        float v2 = __int_as_float(cv2.y), v3 = __int_as_float(cv3.y);
        acc.x += v0 * x0.x; acc.y += v0 * x0.y; acc.z += v0 * x0.z; acc.w += v0 * x0.w;
        acc.x += v1 * x1.x; acc.y += v1 * x1.y; acc.z += v1 * x1.z; acc.w += v1 * x1.w;
        acc.x += v2 * x2.x; acc.y += v2 * x2.y; acc.z += v2 * x2.z; acc.w += v2 * x2.w;
        acc.x += v3 * x3.x; acc.y += v3 * x3.y; acc.z += v3 * x3.z; acc.w += v3 * x3.w;
    }
    for (; e < end; e++) {
        int2 cv = __ldg(&g_ecv[e]);
        float v = __int_as_float(cv.y);
        float4 x = __ldg((const float4*)&X[(size_t)cv.x * D_HID + f4]);
        acc.x += v * x.x; acc.y += v * x.y; acc.z += v * x.z; acc.w += v * x.w;
    }
    acc.x = fmaxf(acc.x, 0.f); acc.y = fmaxf(acc.y, 0.f);
    acc.z = fmaxf(acc.z, 0.f); acc.w = fmaxf(acc.w, 0.f);
    uint2 hi, lo;
    split_f4(acc, hi, lo);
    *(uint2*)&g_H2h[(size_t)r * D_HID + f4] = hi;
    *(uint2*)&g_H2l[(size_t)r * D_HID + f4] = lo;
}

// ---------------- SpMM2: out = spmm(H3), 4-wide unrolled --------------------------
__global__ void k_spmm2(const float* __restrict__ X, float* __restrict__ out) {
    int r = blockIdx.x * 8 + threadIdx.y;
    if (r >= N_NODES) return;
    int f4 = threadIdx.x * 4;               // 32 lanes x 4 feats = 128
    int e   = g_rowptr[r];
    int end = g_rowptr[r + 1];
    float4 acc = make_float4(0.f, 0.f, 0.f, 0.f);
    for (; e + 4 <= end; e += 4) {
        int2 cv0 = __ldg(&g_ecv[e]);
        int2 cv1 = __ldg(&g_ecv[e + 1]);
        int2 cv2 = __ldg(&g_ecv[e + 2]);
        int2 cv3 = __ldg(&g_ecv[e + 3]);
        float4 x0 = __ldg((const float4*)&X[(size_t)cv0.x * D_OUT + f4]);
        float4 x1 = __ldg((const float4*)&X[(size_t)cv1.x * D_OUT + f4]);
        float4 x2 = __ldg((const float4*)&X[(size_t)cv2.x * D_OUT + f4]);
        float4 x3 = __ldg((const float4*)&X[(size_t)cv3.x * D_OUT + f4]);
        float v0 = __int_as_float(cv0.y), v1 = __int_as_float(cv1.y);
        float v2 = __int_as_float(cv2.y), v3 = __int_as_float(cv3.y);
        acc.x += v0 * x0.x; acc.y += v0 * x0.y; acc.z += v0 * x0.z; acc.w += v0 * x0.w;
        acc.x += v1 * x1.x; acc.y += v1 * x1.y; acc.z += v1 * x1.z; acc.w += v1 * x1.w;
        acc.x += v2 * x2.x; acc.y += v2 * x2.y; acc.z += v2 * x2.z; acc.w += v2 * x2.w;
        acc.x += v3 * x3.x; acc.y += v3 * x3.y; acc.z += v3 * x3.z; acc.w += v3 * x3.w;
    }
    for (; e < end; e++) {
        int2 cv = __ldg(&g_ecv[e]);
        float v = __int_as_float(cv.y);
        float4 x = __ldg((const float4*)&X[(size_t)cv.x * D_OUT + f4]);
        acc.x += v * x.x; acc.y += v * x.y; acc.z += v * x.z; acc.w += v * x.w;
    }
    *(float4*)&out[(size_t)r * D_OUT + f4] = acc;
}

// ---------------- launch -----------------------------------------------------------
extern "C" void kernel_launch(void* const* d_in, const int* in_sizes, int n_in,
                              void* d_out, int out_size) {
    const float* Y        = (const float*)d_in[0];
    const int*   edge_row = (const int*)d_in[1];
    const int*   edge_col = (const int*)d_in[2];
    const float* edge_val = (const float*)d_in[3];
    const float* W1       = (const float*)d_in[4];
    const float* W2       = (const float*)d_in[5];
    float*       out      = (float*)d_out;

    float *pH1, *pH3;
    int *pRowptr;
    cudaGetSymbolAddress((void**)&pH1, g_H1);
    cudaGetSymbolAddress((void**)&pH3, g_H3);
    cudaGetSymbolAddress((void**)&pRowptr, g_rowptr);

    const int DSM = NSTG * STG;   // 98304 B
    cudaFuncSetAttribute(k_gemm1_scatter,
                         cudaFuncAttributeMaxDynamicSharedMemorySize, DSM);
    cudaFuncSetAttribute(k_gemm2,
                         cudaFuncAttributeMaxDynamicSharedMemorySize, DSM);

    cudaMemsetAsync(pRowptr, 0, (N_NODES + 1) * sizeof(int));
    k_init_all<<<HISTB + 256 + 128 + YSPB, 256>>>(edge_row, W1, W2, Y);
    k_scan1<<<196, 256>>>();
    k_scan3<<<196, 256>>>();
    k_gemm1_scatter<<<G1B, 256, DSM>>>(pH1, edge_row, edge_col, edge_val);
    {
        dim3 blk(64, 4);
        k_spmm1<<<(N_NODES + 3) / 4, blk>>>(pH1);
    }
    k_gemm2<<<GRID_M, 256, DSM>>>(pH3);
    {
        dim3 blk(32, 8);
        k_spmm2<<<(N_NODES + 7) / 8, blk>>>(pH3, out);
    }
}